// round 2
// baseline (speedup 1.0000x reference)
#include <cuda_runtime.h>
#include <cstdint>
#include <cstddef>

// Problem dims (fixed per reference)
#define DIMM      1024
#define DIM_INNER 2048
#define BATCH     4
#define SEQ       4096
#define MROWS     (BATCH * SEQ)        // 16384
#define HG_COLS   (2 * DIM_INNER)      // 4096

// Scratch: hg = x @ W_hg  [16384, 4096], h (scan output) [16384, 2048]
__device__ float g_hg[(size_t)MROWS * HG_COLS];
__device__ float g_h [(size_t)MROWS * DIM_INNER];

// ---------------------------------------------------------------------------
// Classic tiled SGEMM: C[M,N] = A[M,K] * B[K,N], all row-major, dims divisible
// by tile sizes (16384 / 4096 / 2048 / 1024 all are).
// BM=BN=128, BK=16, 256 threads, 8x8 per-thread tile.
// ---------------------------------------------------------------------------
#define BM 128
#define BN 128
#define BK 16
#define TM 8
#define TN 8

__global__ void __launch_bounds__(256, 2)
sgemm_kernel(const float* __restrict__ A, const float* __restrict__ B,
             float* __restrict__ C, int M, int N, int K)
{
    __shared__ float As[BK][BM];
    __shared__ float Bs[BK][BN];

    const int tid = threadIdx.x;
    const int ty  = tid >> 4;          // 0..15
    const int tx  = tid & 15;          // 0..15
    const int row0 = blockIdx.y * BM;
    const int col0 = blockIdx.x * BN;

    // A tile load mapping: 128 rows x 16 cols = 512 float4; 2 per thread
    const int a_row = tid >> 2;        // 0..63
    const int a_col = (tid & 3) * 4;   // 0,4,8,12
    // B tile load mapping: 16 rows x 128 cols = 512 float4; 2 per thread
    const int b_row = tid >> 5;        // 0..7
    const int b_col = (tid & 31) * 4;  // 0..124

    const float* Ag = A + (size_t)row0 * K;
    const float* Bg = B + col0;

    float acc[TM][TN];
#pragma unroll
    for (int i = 0; i < TM; i++)
#pragma unroll
        for (int j = 0; j < TN; j++) acc[i][j] = 0.0f;

    for (int kt = 0; kt < K; kt += BK) {
        // Load A tile (transposed into smem)
        float4 a0 = *(const float4*)(Ag + (size_t)(a_row)      * K + kt + a_col);
        float4 a1 = *(const float4*)(Ag + (size_t)(a_row + 64) * K + kt + a_col);
        As[a_col + 0][a_row]      = a0.x;
        As[a_col + 1][a_row]      = a0.y;
        As[a_col + 2][a_row]      = a0.z;
        As[a_col + 3][a_row]      = a0.w;
        As[a_col + 0][a_row + 64] = a1.x;
        As[a_col + 1][a_row + 64] = a1.y;
        As[a_col + 2][a_row + 64] = a1.z;
        As[a_col + 3][a_row + 64] = a1.w;
        // Load B tile (direct)
        float4 b0 = *(const float4*)(Bg + (size_t)(kt + b_row)     * N + b_col);
        float4 b1 = *(const float4*)(Bg + (size_t)(kt + b_row + 8) * N + b_col);
        *(float4*)&Bs[b_row][b_col]     = b0;
        *(float4*)&Bs[b_row + 8][b_col] = b1;

        __syncthreads();

#pragma unroll
        for (int k = 0; k < BK; k++) {
            float a[TM], b[TN];
            float4 av0 = *(const float4*)&As[k][ty * TM];
            float4 av1 = *(const float4*)&As[k][ty * TM + 4];
            float4 bv0 = *(const float4*)&Bs[k][tx * TN];
            float4 bv1 = *(const float4*)&Bs[k][tx * TN + 4];
            a[0] = av0.x; a[1] = av0.y; a[2] = av0.z; a[3] = av0.w;
            a[4] = av1.x; a[5] = av1.y; a[6] = av1.z; a[7] = av1.w;
            b[0] = bv0.x; b[1] = bv0.y; b[2] = bv0.z; b[3] = bv0.w;
            b[4] = bv1.x; b[5] = bv1.y; b[6] = bv1.z; b[7] = bv1.w;
#pragma unroll
            for (int i = 0; i < TM; i++)
#pragma unroll
                for (int j = 0; j < TN; j++)
                    acc[i][j] = fmaf(a[i], b[j], acc[i][j]);
        }
        __syncthreads();
    }

    // Store C
#pragma unroll
    for (int i = 0; i < TM; i++) {
        float* Cp = C + (size_t)(row0 + ty * TM + i) * N + col0 + tx * TN;
        float4 v0 = make_float4(acc[i][0], acc[i][1], acc[i][2], acc[i][3]);
        float4 v1 = make_float4(acc[i][4], acc[i][5], acc[i][6], acc[i][7]);
        *(float4*)(Cp)     = v0;
        *(float4*)(Cp + 4) = v1;
    }
}

// ---------------------------------------------------------------------------
// minGRU scan in LINEAR space (mathematically identical to the log-space
// Heinsen scan for these inputs; all quantities positive & bounded):
//   z_t = sigmoid(gate_t)
//   h_t = (1 - z_t) * h_{t-1} + z_t * (relu(hidden_t) + 0.5)
//       = h_{t-1} + z_t * ((relu(hidden_t)+0.5) - h_{t-1})
// One thread per (batch, channel); coalesced loads across channels.
// ---------------------------------------------------------------------------
__global__ void __launch_bounds__(64)
scan_kernel(const float* __restrict__ hg, float* __restrict__ hout)
{
    const int ch = blockIdx.x * blockDim.x + threadIdx.x;  // 0..8191
    const int b  = ch >> 11;           // / DIM_INNER
    const int c  = ch & (DIM_INNER - 1);

    const float* hgp = hg   + (size_t)b * SEQ * HG_COLS;
    float*       hp  = hout + (size_t)b * SEQ * DIM_INNER;

    float h = 0.0f;
    for (int t = 0; t < SEQ; t += 4) {
        float hid[4], gat[4];
#pragma unroll
        for (int u = 0; u < 4; u++) {
            hid[u] = hgp[(size_t)(t + u) * HG_COLS + c];
            gat[u] = hgp[(size_t)(t + u) * HG_COLS + DIM_INNER + c];
        }
#pragma unroll
        for (int u = 0; u < 4; u++) {
            float e = __expf(-gat[u]);
            float z = __fdividef(1.0f, 1.0f + e);
            float uu = fmaxf(hid[u], 0.0f) + 0.5f;
            h = fmaf(z, uu - h, h);
            hp[(size_t)(t + u) * DIM_INNER + c] = h;
        }
    }
}

// ---------------------------------------------------------------------------
// kernel_launch
// Inputs (metadata order): x [4,4096,1024] f32, W_hg [1024,4096] f32,
//                          W_out [2048,1024] f32. Output: [4,4096,1024] f32.
// ---------------------------------------------------------------------------
extern "C" void kernel_launch(void* const* d_in, const int* in_sizes, int n_in,
                              void* d_out, int out_size)
{
    const float* x     = (const float*)d_in[0];
    const float* W_hg  = (const float*)d_in[1];
    const float* W_out = (const float*)d_in[2];
    float*       out   = (float*)d_out;

    void* p_hg = nullptr;
    void* p_h  = nullptr;
    cudaGetSymbolAddress(&p_hg, g_hg);
    cudaGetSymbolAddress(&p_h,  g_h);

    // GEMM1: hg = x @ W_hg   [16384,1024] x [1024,4096]
    {
        dim3 grid(HG_COLS / BN, MROWS / BM);
        sgemm_kernel<<<grid, 256>>>(x, W_hg, (float*)p_hg, MROWS, HG_COLS, DIMM);
    }
    // Scan: 8192 channels, one thread each, spread over many SMs
    {
        int nch = BATCH * DIM_INNER;   // 8192
        scan_kernel<<<nch / 64, 64>>>((const float*)p_hg, (float*)p_h);
    }
    // GEMM2: out = h @ W_out  [16384,2048] x [2048,1024]
    {
        dim3 grid(DIMM / BN, MROWS / BM);
        sgemm_kernel<<<grid, 256>>>((const float*)p_h, W_out, out, MROWS, DIMM, DIM_INNER);
    }
}